// round 5
// baseline (speedup 1.0000x reference)
#include <cuda_runtime.h>
#include <cstdint>

// ProdEinsumTC: out[a,b,c,d,g] = (1/3) * sum_{e,f} T1[a,b,c,d,e,f] * T2[b,c,e,f,g]
// T1: (4, 131072, 6, 27) fp32   T2: (131072, 6, 27) fp32   out: (4, 131072, 6, 9)
//
// R5: R2 structure (warp-autonomous, issue-once-retire) but tuned for 64 warps/SM:
//  - WBC=4 -> smem 17.3KB/block -> 8 blocks/SM; __launch_bounds__(256,8) forces
//    regs<=32 -> occupancy cap 100% (vs 75% in R2).
//  - 32 lanes = 4 paths x 4 bc x 2 halves; each half computes 5 or 4 of the 9
//    outputs (compute pipe is ~11% busy; duplicated t2 reads are free).
//  - Loads: 5 segments x 27 float4, lane<27, cp.async.cg, coalesced & 16B aligned.
//  - Stores: contiguous 144B per (a) per warp -> sectors fully covered.

#define BC        786432
#define BC27      ((size_t)BC * 27)
#define BC9       ((size_t)BC * 9)
#define WBC       4                  // bc pairs per warp
#define WARPS     8                  // warps per block
#define NTHREADS  (WARPS * 32)
#define WARP_F    (WBC * 27 * 5)     // 540 floats per warp region (4xT1 + T2)
#define NORM      (0.3333333333333333f)

__device__ __forceinline__ void cp_async16(uint32_t dst, const void* src) {
    asm volatile("cp.async.cg.shared.global [%0], [%1], 16;\n"
                 :: "r"(dst), "l"(src));
}
__device__ __forceinline__ uint32_t smem_u32(const void* p) {
    uint32_t a;
    asm("{ .reg .u64 t; cvta.to.shared.u64 t, %1; cvt.u32.u64 %0, t; }"
        : "=r"(a) : "l"(p));
    return a;
}

__global__ __launch_bounds__(NTHREADS, 8)
void prod_einsum_kernel(const float* __restrict__ T1,
                        const float* __restrict__ T2,
                        float* __restrict__ out)
{
    __shared__ __align__(16) float smem[WARPS * WARP_F];   // 17280 B

    const int tid  = threadIdx.x;
    const int w    = tid >> 5;
    const int lane = tid & 31;

    float* const swarp = smem + w * WARP_F;
    const uint32_t sw_u32 = smem_u32(swarp);

    const size_t bc0 = ((size_t)blockIdx.x * WARPS + w) * WBC;

    // ---- Stage: 5 segments x 27 float4 (432B each), lane<27 one cp.async ----
    // Layout: [a=0..3][bc][27] floats, then [T2][bc][27] at offset 432 floats.
    if (lane < 27) {
        #pragma unroll
        for (int a = 0; a < 4; ++a) {
            const float4* __restrict__ g1 =
                (const float4*)(T1 + (size_t)a * BC27 + bc0 * 27);
            cp_async16(sw_u32 + (a * 27 + lane) * 16, g1 + lane);
        }
        const float4* __restrict__ g2 = (const float4*)(T2 + bc0 * 27);
        cp_async16(sw_u32 + (108 + lane) * 16, g2 + lane);
    }
    asm volatile("cp.async.commit_group;\n");
    asm volatile("cp.async.wait_group 0;\n" ::: "memory");
    __syncwarp();

    // ---- Compute: lane = (a, bc, h). h=0 -> outputs 0..4, h=1 -> outputs 5..8 ----
    const int a  = lane >> 3;           // 0..3
    const int bc = (lane >> 1) & 3;     // 0..3
    const int h  = lane & 1;            // 0..1

    const float* __restrict__ t1p = swarp + a * 108 + bc * 27;  // [d][e][f]
    const float* __restrict__ t2p = swarp + 432 + bc * 27;      // [e][f][g]

    // h=0 computes (d,g) pairs for flat o=0..4 (d=0 all g; d=1 g=0,1)
    // h=1 computes o=5..8 (d=1 g=2; d=2 all g)
    float acc[5];
    #pragma unroll
    for (int i = 0; i < 5; ++i) acc[i] = 0.0f;
    const int obase = h * 5;
    const int nout  = 5 - h;            // 5 or 4

    #pragma unroll
    for (int k = 0; k < 9; ++k) {       // k = e*3 + f
        const float b0 = t2p[k * 3 + 0];
        const float b1 = t2p[k * 3 + 1];
        const float b2 = t2p[k * 3 + 2];
        const float bg[3] = {b0, b1, b2};
        // d values needed: h=0 -> d=0,1 ; h=1 -> d=1,2
        const float a0 = t1p[(h + 0) * 9 + k];
        const float a1 = t1p[(h + 1) * 9 + k];
        #pragma unroll
        for (int i = 0; i < 5; ++i) {
            if (i < nout) {
                const int o = obase + i;
                const int d = o / 3;            // compile-time after unroll
                const int g = o % 3;
                const float av = (d == h) ? a0 : a1;
                acc[i] = fmaf(av, bg[g], acc[i]);
            }
        }
    }

    __syncwarp();

    // ---- Store: each (a,bc) pair's 9 floats split 5/4 across the h pair;
    //      per path a the warp covers a contiguous 144B run. ----
    float* __restrict__ o = out + (size_t)a * BC9 + (bc0 + bc) * 9 + obase;
    #pragma unroll
    for (int i = 0; i < 5; ++i)
        if (i < nout) o[i] = acc[i] * NORM;
}

extern "C" void kernel_launch(void* const* d_in, const int* in_sizes, int n_in,
                              void* d_out, int out_size)
{
    const float* T1 = (const float*)d_in[0];
    const float* T2 = (const float*)d_in[1];
    float* out = (float*)d_out;

    const int nblocks = BC / (WARPS * WBC);   // 24576
    prod_einsum_kernel<<<nblocks, NTHREADS>>>(T1, T2, out);
}

// round 6
// speedup vs baseline: 1.6689x; 1.6689x over previous
#include <cuda_runtime.h>
#include <cstdint>

// ProdEinsumTC: out[a,b,c,d,g] = (1/3) * sum_{e,f} T1[a,b,c,d,e,f] * T2[b,c,e,f,g]
// T1: (4, 131072, 6, 27) fp32   T2: (131072, 6, 27) fp32   out: (4, 131072, 6, 9)
//
// R6: depth-2 double-buffered warp pipeline, R2 compute map.
//  - 128-thread blocks, 4 warps; each warp: 2 x 4.32KB buffers, 4 consecutive
//    8-bc tiles. Prologue issues 2 groups; each iter: wait_group 1 -> compute
//    (32-lane, 54 LDS, 81 FMA) -> syncwarp -> reissue into consumed buffer ->
//    direct stores. One group per warp is ALWAYS in flight (usually two).
//  - 34.56KB smem/block -> 6 blocks/SM -> full 207KB of buffers cycling.

#define BC        786432
#define BC27      ((size_t)BC * 27)
#define BC9       ((size_t)BC * 9)
#define WBC       8                    // bc pairs per tile
#define TPW       4                    // tiles per warp
#define WARPS     4                    // warps per block
#define NTHREADS  (WARPS * 32)
#define BUF_F     (WBC * 27 * 5)       // 1080 floats per buffer
#define NORM      (0.3333333333333333f)

__device__ __forceinline__ void cp_async16(uint32_t dst, const void* src) {
    asm volatile("cp.async.cg.shared.global [%0], [%1], 16;\n"
                 :: "r"(dst), "l"(src));
}
__device__ __forceinline__ uint32_t smem_u32(const void* p) {
    uint32_t a;
    asm("{ .reg .u64 t; cvta.to.shared.u64 t, %1; cvt.u32.u64 %0, t; }"
        : "=r"(a) : "l"(p));
    return a;
}

// Issue one 8-bc tile (4 T1 segments + T2 = 270 float4) into a buffer.
__device__ __forceinline__ void issue_tile(const float* __restrict__ T1,
                                           const float* __restrict__ T2,
                                           size_t bc0, uint32_t buf_u32, int lane)
{
    #pragma unroll
    for (int a = 0; a < 4; ++a) {
        const float4* __restrict__ g1 =
            (const float4*)(T1 + (size_t)a * BC27 + bc0 * 27);
        cp_async16(buf_u32 + (a * 54 + lane) * 16, g1 + lane);
        if (lane < 22)
            cp_async16(buf_u32 + (a * 54 + 32 + lane) * 16, g1 + 32 + lane);
    }
    const float4* __restrict__ g2 = (const float4*)(T2 + bc0 * 27);
    cp_async16(buf_u32 + (216 + lane) * 16, g2 + lane);
    if (lane < 22)
        cp_async16(buf_u32 + (216 + 32 + lane) * 16, g2 + 32 + lane);
    asm volatile("cp.async.commit_group;\n");
}

__global__ __launch_bounds__(NTHREADS, 6)
void prod_einsum_kernel(const float* __restrict__ T1,
                        const float* __restrict__ T2,
                        float* __restrict__ out)
{
    __shared__ __align__(16) float smem[WARPS * 2 * BUF_F];   // 34560 B

    const int tid  = threadIdx.x;
    const int w    = tid >> 5;
    const int lane = tid & 31;
    const int a    = lane >> 3;     // 0..3
    const int bcl  = lane & 7;      // 0..7

    float* const wbase = smem + w * 2 * BUF_F;
    const uint32_t wbase_u32 = smem_u32(wbase);

    // This warp's 4 consecutive tiles start here:
    const size_t t0 = ((size_t)blockIdx.x * WARPS + w) * TPW;

    // ---- Prologue: fill both pipeline stages ----
    issue_tile(T1, T2, (t0 + 0) * WBC, wbase_u32, lane);
    issue_tile(T1, T2, (t0 + 1) * WBC, wbase_u32 + BUF_F * 4, lane);

    #pragma unroll
    for (int i = 0; i < TPW; ++i) {
        const size_t bc0 = (t0 + i) * WBC;
        float* const buf = wbase + (i & 1) * BUF_F;

        // Wait for group i; keep the next group in flight.
        if (i < TPW - 1)
            asm volatile("cp.async.wait_group 1;\n" ::: "memory");
        else
            asm volatile("cp.async.wait_group 0;\n" ::: "memory");
        __syncwarp();

        // ---- Compute: 54 conflict-free LDS.32, 81 FMA ----
        const float* __restrict__ t1p = buf + a * 216 + bcl * 27;  // [d][e][f]
        const float* __restrict__ t2p = buf + 864 + bcl * 27;      // [e][f][g]

        float acc[9];
        #pragma unroll
        for (int j = 0; j < 9; ++j) acc[j] = 0.0f;

        #pragma unroll
        for (int k = 0; k < 9; ++k) {                 // k = e*3 + f
            const float b0 = t2p[k * 3 + 0];
            const float b1 = t2p[k * 3 + 1];
            const float b2 = t2p[k * 3 + 2];
            #pragma unroll
            for (int d = 0; d < 3; ++d) {
                const float av = t1p[d * 9 + k];
                acc[d * 3 + 0] = fmaf(av, b0, acc[d * 3 + 0]);
                acc[d * 3 + 1] = fmaf(av, b1, acc[d * 3 + 1]);
                acc[d * 3 + 2] = fmaf(av, b2, acc[d * 3 + 2]);
            }
        }

        __syncwarp();   // all lanes done reading buf -> safe to refill

        // ---- Refill the just-consumed buffer ASAP (loads fly under stores) ----
        if (i + 2 < TPW)
            issue_tile(T1, T2, (t0 + i + 2) * WBC, smem_u32(buf), lane);

        // ---- Store: 9 contiguous floats/thread; per path the warp covers a
        //      contiguous 288B run -> sectors fully covered, merged in LTS ----
        float* __restrict__ o = out + (size_t)a * BC9 + (bc0 + bcl) * 9;
        #pragma unroll
        for (int j = 0; j < 9; ++j)
            o[j] = acc[j] * NORM;
    }
}

extern "C" void kernel_launch(void* const* d_in, const int* in_sizes, int n_in,
                              void* d_out, int out_size)
{
    const float* T1 = (const float*)d_in[0];
    const float* T2 = (const float*)d_in[1];
    float* out = (float*)d_out;

    // 786432 bc / (4 warps * 4 tiles * 8 bc) = 6144 blocks
    const int nblocks = BC / (WARPS * TPW * WBC);
    prod_einsum_kernel<<<nblocks, NTHREADS>>>(T1, T2, out);
}

// round 7
// speedup vs baseline: 2.0947x; 1.2552x over previous
#include <cuda_runtime.h>
#include <cstdint>

// ProdEinsumTC: out[a,b,c,d,g] = (1/3) * sum_{e,f} T1[a,b,c,d,e,f] * T2[b,c,e,f,g]
// T1: (4, 131072, 6, 27) fp32   T2: (131072, 6, 27) fp32   out: (4, 131072, 6, 9)
//
// R7: R2's proven warp-autonomous issue-once structure, re-blocked at 128
// threads (4 warps, 17.28KB smem) with launch_bounds(128,12):
//  - 12 blocks/SM x 4 warps = 48 resident warps (same cap as R2) but the
//    CTA scheduling quantum is halved -> smaller churn holes, faster backfill.
//  - Per-warp code identical to the 80.6us R2 kernel: cp.async.cg float4
//    stage, conflict-free stride-27 LDS, 81 FMA, smem-staged STG.128 output.

#define BC        786432
#define BC27      ((size_t)BC * 27)
#define BC9       ((size_t)BC * 9)
#define WBC       8                 // bc pairs per warp
#define WARPS     4                 // warps per block
#define NTHREADS  (WARPS * 32)
#define WARP_F    (WBC * 27 * 5)    // 1080 floats per warp region (4xT1 + T2)
#define NORM      (0.3333333333333333f)

__device__ __forceinline__ void cp_async16(uint32_t dst, const void* src) {
    asm volatile("cp.async.cg.shared.global [%0], [%1], 16;\n"
                 :: "r"(dst), "l"(src));
}
__device__ __forceinline__ uint32_t smem_u32(const void* p) {
    uint32_t a;
    asm("{ .reg .u64 t; cvta.to.shared.u64 t, %1; cvt.u32.u64 %0, t; }"
        : "=r"(a) : "l"(p));
    return a;
}

__global__ __launch_bounds__(NTHREADS, 12)
void prod_einsum_kernel(const float* __restrict__ T1,
                        const float* __restrict__ T2,
                        float* __restrict__ out)
{
    __shared__ __align__(16) float smem[WARPS * WARP_F];   // 17280 B

    const int tid  = threadIdx.x;
    const int w    = tid >> 5;
    const int lane = tid & 31;

    float* const swarp = smem + w * WARP_F;
    const uint32_t sw_u32 = smem_u32(swarp);

    const size_t bc0 = ((size_t)blockIdx.x * WARPS + w) * WBC;

    // ---- Stage: 5 segments x 54 float4, all coalesced & 16B-aligned ----
    // Layout: [a=0..3][bcl][27] then [T2][bcl][27]
    #pragma unroll
    for (int a = 0; a < 4; ++a) {
        const float4* __restrict__ g1 =
            (const float4*)(T1 + (size_t)a * BC27 + bc0 * 27);
        cp_async16(sw_u32 + (a * 54 + lane) * 16, g1 + lane);
        if (lane < 22)
            cp_async16(sw_u32 + (a * 54 + 32 + lane) * 16, g1 + 32 + lane);
    }
    {
        const float4* __restrict__ g2 = (const float4*)(T2 + bc0 * 27);
        cp_async16(sw_u32 + (216 + lane) * 16, g2 + lane);
        if (lane < 22)
            cp_async16(sw_u32 + (216 + 32 + lane) * 16, g2 + 32 + lane);
    }
    asm volatile("cp.async.commit_group;\n");
    asm volatile("cp.async.wait_group 0;\n" ::: "memory");
    __syncwarp();

    // ---- Compute: lane = (a, bcl). 54 conflict-free LDS.32, 81 FMA ----
    const int a   = lane >> 3;     // 0..3
    const int bcl = lane & 7;      // 0..7

    const float* __restrict__ t1p = swarp + a * 216 + bcl * 27;  // [d][e][f]
    const float* __restrict__ t2p = swarp + 864 + bcl * 27;      // [e][f][g]

    float acc[9];
    #pragma unroll
    for (int i = 0; i < 9; ++i) acc[i] = 0.0f;

    #pragma unroll
    for (int k = 0; k < 9; ++k) {                 // k = e*3 + f
        const float b0 = t2p[k * 3 + 0];
        const float b1 = t2p[k * 3 + 1];
        const float b2 = t2p[k * 3 + 2];
        #pragma unroll
        for (int d = 0; d < 3; ++d) {
            const float av = t1p[d * 9 + k];
            acc[d * 3 + 0] = fmaf(av, b0, acc[d * 3 + 0]);
            acc[d * 3 + 1] = fmaf(av, b1, acc[d * 3 + 1]);
            acc[d * 3 + 2] = fmaf(av, b2, acc[d * 3 + 2]);
        }
    }

    // ---- Store: stage in smem, then STG.128 coalesced ----
    __syncwarp();                   // all compute reads of swarp done
    #pragma unroll
    for (int j = 0; j < 9; ++j)     // stride-9 STS.32: conflict-free
        swarp[lane * 9 + j] = acc[j] * NORM;
    __syncwarp();

    #pragma unroll
    for (int aa = 0; aa < 4; ++aa) {
        float4* __restrict__ o = (float4*)(out + (size_t)aa * BC9 + bc0 * 9);
        if (lane < 18)              // 72 floats = 18 float4 per path
            o[lane] = *(const float4*)(swarp + aa * 72 + lane * 4);
    }
}

extern "C" void kernel_launch(void* const* d_in, const int* in_sizes, int n_in,
                              void* d_out, int out_size)
{
    const float* T1 = (const float*)d_in[0];
    const float* T2 = (const float*)d_in[1];
    float* out = (float*)d_out;

    const int nblocks = BC / (WARPS * WBC);   // 24576
    prod_einsum_kernel<<<nblocks, NTHREADS>>>(T1, T2, out);
}